// round 14
// baseline (speedup 1.0000x reference)
#include <cuda_runtime.h>
#include <cuda_bf16.h>

// ---------------------------------------------------------------------------
// DeformConv fused pipeline, round 14:
//  - k_gemm v2: 1m x 16n warp layout (warp tile 128x16) — halves B L2 traffic.
//  - k_prep, k_offmma, k_norm byte-identical to R13.
// ---------------------------------------------------------------------------

#define HH 96
#define WW 96
#define SS 9216
#define NB 4
#define CIN 256
#define COUT 256
#define M_TOTAL (NB * SS)      // 36864
#define KDIM (9 * CIN)         // 2304
#define NKT 72                 // k32 tiles

// Scratch
__device__ __align__(16) float g_xT[NB * SS * CIN];        // NHWC x
__device__ __align__(16) uint4 g_wFa[288 * 8 * 32];        // main B frags f0,f1
__device__ __align__(16) uint4 g_wFb[288 * 8 * 32];        // main B frags f2,f3
__device__ __align__(16) uint4 g_wOffF[288 * 2 * 32];      // offset B frags
__device__ __align__(16) float4 g_pw[9 * M_TOTAL];
__device__ __align__(16) int4   g_pi[9 * M_TOTAL];
__device__ float g_chsum[COUT];
__device__ float g_chsq[COUT];

// ---------------- asm helpers ----------------
#define MMA_TF32(d, a, bx, by) \
    asm volatile("mma.sync.aligned.m16n8k8.row.col.f32.tf32.tf32.f32 " \
                 "{%0,%1,%2,%3},{%4,%5,%6,%7},{%8,%9},{%0,%1,%2,%3};" \
                 : "+f"((d)[0]), "+f"((d)[1]), "+f"((d)[2]), "+f"((d)[3]) \
                 : "r"((a)[0]), "r"((a)[1]), "r"((a)[2]), "r"((a)[3]), \
                   "r"(bx), "r"(by))

__device__ __forceinline__ unsigned f2tf(float f) {
    unsigned u;
    asm("cvt.rna.tf32.f32 %0, %1;" : "=r"(u) : "f"(f));
    return u;
}

// ---------------------------------------------------------------------------
// K0: fused prep. Blocks [0,2304): NCHW->NHWC transpose (4 sub-tiles each).
// Blocks [2304,2592): main B frags. Blocks [2592,2664): offset B frags.
// ---------------------------------------------------------------------------
__global__ __launch_bounds__(256) void k_prep(const float* __restrict__ x,
                                              const float* __restrict__ w,
                                              const float* __restrict__ w_off) {
    const int bid = blockIdx.x;
    if (bid < 2304) {
        __shared__ float tile[4][32][33];
        const int bx = bid % 72;
        const int by = (bid / 72) & 7;
        const int bz = bid / 576;
        const int c0 = by * 32;
        const int s0 = bx * 128;
        const int tx = threadIdx.x & 31, ty = threadIdx.x >> 5;
        const float* src = x + (size_t)bz * CIN * SS;

        float r[4][4];
#pragma unroll
        for (int st = 0; st < 4; st++)
#pragma unroll
            for (int i = 0; i < 4; i++)
                r[st][i] = src[(size_t)(c0 + ty + i * 8) * SS + (s0 + st * 32 + tx)];
#pragma unroll
        for (int st = 0; st < 4; st++)
#pragma unroll
            for (int i = 0; i < 4; i++)
                tile[st][ty + i * 8][tx] = r[st][i];
        __syncthreads();

        float* dst = g_xT + (size_t)bz * SS * CIN;
#pragma unroll
        for (int st = 0; st < 4; st++)
#pragma unroll
            for (int i = 0; i < 4; i++)
                dst[(size_t)(s0 + st * 32 + ty + i * 8) * CIN + (c0 + tx)] =
                    tile[st][tx][ty + i * 8];
    } else if (bid < 2592) {
        const int T = (bid - 2304) * 256 + threadIdx.x;
        if (bid == 2304 && threadIdx.x < 256) {
            g_chsum[threadIdx.x] = 0.0f;
            g_chsq[threadIdx.x] = 0.0f;
        }
        const int lane = T & 31;
        const int cb = (T >> 5) & 7;
        const int K8 = T >> 8;
        const int t = K8 >> 2;
        const int tap = t >> 3;
        const int c0 = (t & 7) * 32 + (K8 & 3) * 8 + (lane & 3);
        const int c1 = c0 + 4;
        unsigned r[8];
#pragma unroll
        for (int f = 0; f < 4; f++) {
            const int n = cb * 32 + f * 8 + (lane >> 2);
            r[2 * f]     = f2tf(w[((size_t)n * 256 + c0) * 9 + tap]);
            r[2 * f + 1] = f2tf(w[((size_t)n * 256 + c1) * 9 + tap]);
        }
        g_wFa[(K8 * 8 + cb) * 32 + lane] = make_uint4(r[0], r[1], r[2], r[3]);
        g_wFb[(K8 * 8 + cb) * 32 + lane] = make_uint4(r[4], r[5], r[6], r[7]);
    } else {
        const int T = (bid - 2592) * 256 + threadIdx.x;
        const int lane = T & 31;
        const int wn = (T >> 5) & 1;
        const int K8 = T >> 6;
        const int t = K8 >> 2;
        const int tap = t >> 3;
        const int c0 = (t & 7) * 32 + (K8 & 3) * 8 + (lane & 3);
        const int c1 = c0 + 4;
        unsigned r[4];
#pragma unroll
        for (int fl = 0; fl < 2; fl++) {
            const int n = wn * 16 + fl * 8 + (lane >> 2);
            float v0 = 0.0f, v1 = 0.0f;
            if (n < 27) {
                v0 = w_off[((size_t)n * 256 + c0) * 9 + tap];
                v1 = w_off[((size_t)n * 256 + c1) * 9 + tap];
            }
            r[2 * fl]     = f2tf(v0);
            r[2 * fl + 1] = f2tf(v1);
        }
        g_wOffF[(K8 * 2 + wn) * 32 + lane] = make_uint4(r[0], r[1], r[2], r[3]);
    }
}

// ---------------------------------------------------------------------------
// K1: offset conv as tf32 GEMM + fused bilinear-param epilogue (R13 exact).
// ---------------------------------------------------------------------------
__global__ __launch_bounds__(512, 2) void k_offmma(const float* __restrict__ b_off) {
    __shared__ unsigned Asm[2][128][36];

    const int tid = threadIdx.x;
    const int wid = tid >> 5;
    const int lane = tid & 31;
    const int wm = wid >> 1;
    const int wn = wid & 1;
    const int m0 = blockIdx.x * 128;

    const int pg0 = tid >> 3, pg1 = 64 + pg0;
    const int cp = tid & 7;
    int ph[2], pw_[2], bofs[2], aofs[2];
#pragma unroll
    for (int s = 0; s < 2; s++) {
        const int P = m0 + (s ? pg1 : pg0);
        bofs[s] = (P / SS) * (SS * CIN);
        const int rem = P % SS;
        ph[s] = rem / WW;
        pw_[s] = rem % WW;
    }

    float acc[2][4];
#pragma unroll
    for (int f = 0; f < 2; f++)
#pragma unroll
        for (int c = 0; c < 4; c++) acc[f][c] = 0.0f;

    float4 v[2];

    auto tapsetup = [&](int tap) {
        const int ky = tap / 3 - 1, kx = tap % 3 - 1;
#pragma unroll
        for (int s = 0; s < 2; s++) {
            const int y = ph[s] + ky, x = pw_[s] + kx;
            aofs[s] = (y >= 0 && y < HH && x >= 0 && x < WW)
                          ? bofs[s] + ((y * WW + x) << 8) : -1;
        }
    };
    auto load = [&](int t) {
        const int cb = (t & 7) * 32 + cp * 4;
#pragma unroll
        for (int s = 0; s < 2; s++)
            v[s] = (aofs[s] >= 0) ? *(const float4*)(g_xT + aofs[s] + cb)
                                  : make_float4(0, 0, 0, 0);
    };
    auto store = [&](int buf) {
#pragma unroll
        for (int s = 0; s < 2; s++)
            *(uint4*)&Asm[buf][s ? pg1 : pg0][cp * 4] =
                make_uint4(f2tf(v[s].x), f2tf(v[s].y), f2tf(v[s].z), f2tf(v[s].w));
    };
    auto compute2 = [&](int t, int buf, int q0) {
#pragma unroll
        for (int qq = 0; qq < 2; qq++) {
            const int q = q0 + qq;
            const uint4 B = g_wOffF[((t * 4 + q) * 2 + wn) * 32 + lane];
            const int r = wm * 16 + (lane >> 2);
            const int c = q * 8 + (lane & 3);
            unsigned a[4];
            a[0] = Asm[buf][r][c];
            a[1] = Asm[buf][r + 8][c];
            a[2] = Asm[buf][r][c + 4];
            a[3] = Asm[buf][r + 8][c + 4];
            MMA_TF32(acc[0], a, B.x, B.y);
            MMA_TF32(acc[1], a, B.z, B.w);
        }
    };

    tapsetup(0);
    load(0); store(0);
    __syncthreads();
#pragma unroll 1
    for (int t = 0; t < NKT; t++) {
        const int buf = t & 1;
        const bool more = (t + 1 < NKT);
        if (more && ((t + 1) & 7) == 0) tapsetup((t + 1) >> 3);
        if (more) load(t + 1);
        compute2(t, buf, 0);
        if (more) store(buf ^ 1);
        compute2(t, buf, 2);
        __syncthreads();
    }

    float* E = ((float*)Asm) + wm * (16 * 33);
    const int rr = lane >> 2, cc2 = (lane & 3) * 2;
#pragma unroll
    for (int f = 0; f < 2; f++) {
        const int cbase = wn * 16 + f * 8 + cc2;
        E[rr * 33 + cbase]           = acc[f][0];
        E[rr * 33 + cbase + 1]       = acc[f][1];
        E[(rr + 8) * 33 + cbase]     = acc[f][2];
        E[(rr + 8) * 33 + cbase + 1] = acc[f][3];
    }
    __syncthreads();
    if (wn == 0 && lane < 16) {
        const int P = m0 + wm * 16 + lane;
        const int rem = P % SS;
        const int h = rem / WW, w = rem - (rem / WW) * WW;
        const float* Er = E + lane * 33;
#pragma unroll
        for (int k = 0; k < 9; k++) {
            const float dy = Er[k]      + __ldg(&b_off[k]);
            const float dx = Er[9 + k]  + __ldg(&b_off[9 + k]);
            const float mm = 1.0f / (1.0f + __expf(-(Er[18 + k] + __ldg(&b_off[18 + k]))));
            const float py = (dy + (float)h) + (float)(k / 3 - 1);
            const float px = (dx + (float)w) + (float)(k % 3 - 1);
            const float y0f = floorf(py), x0f = floorf(px);
            const float ly = py - y0f, lx = px - x0f;
            const float vy0 = (y0f >= 0.0f && y0f <= 95.0f) ? 1.0f : 0.0f;
            const float vy1 = (y0f + 1.0f >= 0.0f && y0f + 1.0f <= 95.0f) ? 1.0f : 0.0f;
            const float vx0 = (x0f >= 0.0f && x0f <= 95.0f) ? 1.0f : 0.0f;
            const float vx1 = (x0f + 1.0f >= 0.0f && x0f + 1.0f <= 95.0f) ? 1.0f : 0.0f;
            const int iy0 = (int)fminf(fmaxf(y0f, 0.0f), 95.0f);
            const int iy1 = (int)fminf(fmaxf(y0f + 1.0f, 0.0f), 95.0f);
            const int ix0 = (int)fminf(fmaxf(x0f, 0.0f), 95.0f);
            const int ix1 = (int)fminf(fmaxf(x0f + 1.0f, 0.0f), 95.0f);
            const float w00 = (1.0f - ly) * (1.0f - lx) * vy0 * vx0 * mm;
            const float w01 = (1.0f - ly) * lx          * vy0 * vx1 * mm;
            const float w10 = ly          * (1.0f - lx) * vy1 * vx0 * mm;
            const float w11 = ly          * lx          * vy1 * vx1 * mm;
            g_pw[k * M_TOTAL + P] = make_float4(w00, w01, w10, w11);
            g_pi[k * M_TOTAL + P] = make_int4(iy0 * WW + ix0, iy0 * WW + ix1,
                                              iy1 * WW + ix0, iy1 * WW + ix1);
        }
    }
}

// ---------------------------------------------------------------------------
// K2: main tf32 GEMM v2: 1m x 16n warps (warp tile 128x16), halved B traffic.
// ---------------------------------------------------------------------------
__global__ __launch_bounds__(512, 1) void k_gemm(const float* __restrict__ bvec,
                                                 float* __restrict__ out) {
    __shared__ unsigned Asm[2][128][36];

    const int tid = threadIdx.x;
    const int wid = tid >> 5;
    const int lane = tid & 31;
    const int wn = wid;                 // 0..15, couts wn*16..wn*16+15

    const int m0 = blockIdx.x * 128;
    const int n = m0 / SS;
    const int sb = m0 % SS;
    const float* xbase = g_xT + (size_t)n * SS * CIN;

    const int pg0 = tid >> 3, pg1 = 64 + pg0;
    const int cp = tid & 7;
    const int bbase = (wn >> 1) * 32 + lane;   // B fragment index base
    const int bhalf = wn & 1;                  // 0 -> g_wFa, 1 -> g_wFb

    float acc[8][2][4];
#pragma unroll
    for (int a = 0; a < 8; a++)
#pragma unroll
        for (int b = 0; b < 2; b++)
#pragma unroll
            for (int c = 0; c < 4; c++) acc[a][b][c] = 0.0f;

    float4 pm[2];
    int4 ii[2];
    float4 v[4];

    auto loadS = [&](int s, int t) {
        const int tap = t >> 3, sub = t & 7;
        if (sub == 0 && s == 0) {
            pm[0] = g_pw[tap * M_TOTAL + m0 + pg0];
            ii[0] = g_pi[tap * M_TOTAL + m0 + pg0];
            pm[1] = g_pw[tap * M_TOTAL + m0 + pg1];
            ii[1] = g_pi[tap * M_TOTAL + m0 + pg1];
        }
        const int cb = sub * 32 + cp * 4;
        v[0] = *(const float4*)(xbase + (ii[s].x << 8) + cb);
        v[1] = *(const float4*)(xbase + (ii[s].y << 8) + cb);
        v[2] = *(const float4*)(xbase + (ii[s].z << 8) + cb);
        v[3] = *(const float4*)(xbase + (ii[s].w << 8) + cb);
    };
    auto storeS = [&](int s, int buf) {
        const float4 w4 = pm[s];
        float a0 = w4.x * v[0].x + w4.y * v[1].x + w4.z * v[2].x + w4.w * v[3].x;
        float a1 = w4.x * v[0].y + w4.y * v[1].y + w4.z * v[2].y + w4.w * v[3].y;
        float a2 = w4.x * v[0].z + w4.y * v[1].z + w4.z * v[2].z + w4.w * v[3].z;
        float a3 = w4.x * v[0].w + w4.y * v[1].w + w4.z * v[2].w + w4.w * v[3].w;
        *(uint4*)&Asm[buf][s ? pg1 : pg0][cp * 4] =
            make_uint4(f2tf(a0), f2tf(a1), f2tf(a2), f2tf(a3));
    };
    auto compute_q = [&](int t, int buf, int q) {
        const int bi = (t * 4 + q) * 256 + bbase;
        const uint4 B = bhalf ? g_wFb[bi] : g_wFa[bi];
#pragma unroll
        for (int mt = 0; mt < 8; mt++) {
            const int r = mt * 16 + (lane >> 2);
            const int c = q * 8 + (lane & 3);
            unsigned a[4];
            a[0] = Asm[buf][r][c];
            a[1] = Asm[buf][r + 8][c];
            a[2] = Asm[buf][r][c + 4];
            a[3] = Asm[buf][r + 8][c + 4];
            MMA_TF32(acc[mt][0], a, B.x, B.y);
            MMA_TF32(acc[mt][1], a, B.z, B.w);
        }
    };

    loadS(0, 0); storeS(0, 0);
    loadS(1, 0); storeS(1, 0);
    __syncthreads();
#pragma unroll 1
    for (int t = 0; t < NKT; t++) {
        const int buf = t & 1;
        const int nbuf = (t + 1) & 1;
        const bool more = (t + 1 < NKT);
        if (more) loadS(0, t + 1);
        compute_q(t, buf, 0);
        if (more) { storeS(0, nbuf); loadS(1, t + 1); }
        compute_q(t, buf, 1);
        compute_q(t, buf, 2);
        if (more) storeS(1, nbuf);
        compute_q(t, buf, 3);
        __syncthreads();
    }

    // epilogue: +bias, write pre-BN y, per-thread BN partials
    float* Ssm = (float*)&Asm[0][0][0];          // [256][8]
    float* Qsm = Ssm + 2048;                     // [256][8]
    const int slot = lane >> 2;                  // 0..7
#pragma unroll
    for (int f = 0; f < 2; f++) {
        const int co = wn * 16 + f * 8 + (lane & 3) * 2;
        const float b0 = __ldg(&bvec[co]);
        const float b1 = __ldg(&bvec[co + 1]);
        float* o0 = out + ((size_t)n * COUT + co) * SS + sb + (lane >> 2);
        float* o1 = o0 + SS;
        float s0 = 0, q0 = 0, s1 = 0, q1 = 0;
#pragma unroll
        for (int mt = 0; mt < 8; mt++) {
            const int r = mt * 16;
            float vv;
            vv = acc[mt][f][0] + b0; o0[r]     = vv; s0 += vv; q0 += vv * vv;
            vv = acc[mt][f][1] + b1; o1[r]     = vv; s1 += vv; q1 += vv * vv;
            vv = acc[mt][f][2] + b0; o0[r + 8] = vv; s0 += vv; q0 += vv * vv;
            vv = acc[mt][f][3] + b1; o1[r + 8] = vv; s1 += vv; q1 += vv * vv;
        }
        Ssm[co * 8 + slot] = s0;  Ssm[(co + 1) * 8 + slot] = s1;
        Qsm[co * 8 + slot] = q0;  Qsm[(co + 1) * 8 + slot] = q1;
    }
    __syncthreads();
    if (tid < 256) {
        float s = 0;
#pragma unroll
        for (int j = 0; j < 8; j++) s += Ssm[tid * 8 + j];
        atomicAdd(&g_chsum[tid], s);
    } else {
        float s = 0;
#pragma unroll
        for (int j = 0; j < 8; j++) s += Qsm[(tid - 256) * 8 + j];
        atomicAdd(&g_chsq[tid - 256], s);
    }
}

// ---------------------------------------------------------------------------
// K4: normalize + ReLU in place, BN finalize inlined (R13 exact).
// ---------------------------------------------------------------------------
__global__ __launch_bounds__(256) void k_norm(float* __restrict__ out,
                                              const float* __restrict__ gamma,
                                              const float* __restrict__ beta) {
    const int co = blockIdx.x & 255;
    const float inv = 1.0f / (float)M_TOTAL;
    const float mean = g_chsum[co] * inv;
    const float var = g_chsq[co] * inv - mean * mean;
    const float sc = __ldg(&gamma[co]) * rsqrtf(var + 1e-5f);
    const float sh = __ldg(&beta[co]) - mean * sc;

    float4* p = (float4*)(out + (size_t)blockIdx.x * SS) + threadIdx.x;
    float4 v[9];
#pragma unroll
    for (int i = 0; i < 9; i++) v[i] = p[i * 256];
#pragma unroll
    for (int i = 0; i < 9; i++) {
        v[i].x = fmaxf(v[i].x * sc + sh, 0.0f);
        v[i].y = fmaxf(v[i].y * sc + sh, 0.0f);
        v[i].z = fmaxf(v[i].z * sc + sh, 0.0f);
        v[i].w = fmaxf(v[i].w * sc + sh, 0.0f);
        p[i * 256] = v[i];
    }
}

// ---------------------------------------------------------------------------
extern "C" void kernel_launch(void* const* d_in, const int* in_sizes, int n_in,
                              void* d_out, int out_size) {
    (void)in_sizes; (void)n_in; (void)out_size;
    const float* x     = (const float*)d_in[0];
    const float* w_off = (const float*)d_in[1];
    const float* b_off = (const float*)d_in[2];
    const float* w     = (const float*)d_in[3];
    const float* b     = (const float*)d_in[4];
    const float* gamma = (const float*)d_in[5];
    const float* beta  = (const float*)d_in[6];
    float* out = (float*)d_out;

    k_prep<<<2664, 256>>>(x, w, w_off);
    k_offmma<<<M_TOTAL / 128, 512>>>(b_off);
    k_gemm<<<M_TOTAL / 128, 512>>>(b, out);
    k_norm<<<NB * COUT, 256>>>(out, gamma, beta);
}

// round 15
// speedup vs baseline: 1.0704x; 1.0704x over previous
#include <cuda_runtime.h>
#include <cuda_bf16.h>

// ---------------------------------------------------------------------------
// DeformConv fused pipeline, round 15: byte-exact R13 restore (best: 405.6us).
//  - k_prep: fused transpose + wprep + woffprep.
//  - k_offmma: tf32 GEMM, hoisted tap math, narrow prefetch, fused params.
//  - k_gemm: tf32 GEMM, 2m x 8n warps, narrow-window pipeline, fused BN sums.
//  - k_norm: BN finalize inlined + ReLU.
// ---------------------------------------------------------------------------

#define HH 96
#define WW 96
#define SS 9216
#define NB 4
#define CIN 256
#define COUT 256
#define M_TOTAL (NB * SS)      // 36864
#define KDIM (9 * CIN)         // 2304
#define NKT 72                 // k32 tiles

// Scratch
__device__ __align__(16) float g_xT[NB * SS * CIN];        // NHWC x
__device__ __align__(16) uint4 g_wFa[288 * 8 * 32];        // main B frags f0,f1
__device__ __align__(16) uint4 g_wFb[288 * 8 * 32];        // main B frags f2,f3
__device__ __align__(16) uint4 g_wOffF[288 * 2 * 32];      // offset B frags
__device__ __align__(16) float4 g_pw[9 * M_TOTAL];
__device__ __align__(16) int4   g_pi[9 * M_TOTAL];
__device__ float g_chsum[COUT];
__device__ float g_chsq[COUT];

// ---------------- asm helpers ----------------
#define MMA_TF32(d, a, bx, by) \
    asm volatile("mma.sync.aligned.m16n8k8.row.col.f32.tf32.tf32.f32 " \
                 "{%0,%1,%2,%3},{%4,%5,%6,%7},{%8,%9},{%0,%1,%2,%3};" \
                 : "+f"((d)[0]), "+f"((d)[1]), "+f"((d)[2]), "+f"((d)[3]) \
                 : "r"((a)[0]), "r"((a)[1]), "r"((a)[2]), "r"((a)[3]), \
                   "r"(bx), "r"(by))

__device__ __forceinline__ unsigned f2tf(float f) {
    unsigned u;
    asm("cvt.rna.tf32.f32 %0, %1;" : "=r"(u) : "f"(f));
    return u;
}

// ---------------------------------------------------------------------------
// K0: fused prep. Blocks [0,2304): NCHW->NHWC transpose (4 sub-tiles each).
// Blocks [2304,2592): main B frags. Blocks [2592,2664): offset B frags.
// ---------------------------------------------------------------------------
__global__ __launch_bounds__(256) void k_prep(const float* __restrict__ x,
                                              const float* __restrict__ w,
                                              const float* __restrict__ w_off) {
    const int bid = blockIdx.x;
    if (bid < 2304) {
        __shared__ float tile[4][32][33];
        const int bx = bid % 72;
        const int by = (bid / 72) & 7;
        const int bz = bid / 576;
        const int c0 = by * 32;
        const int s0 = bx * 128;
        const int tx = threadIdx.x & 31, ty = threadIdx.x >> 5;
        const float* src = x + (size_t)bz * CIN * SS;

        float r[4][4];
#pragma unroll
        for (int st = 0; st < 4; st++)
#pragma unroll
            for (int i = 0; i < 4; i++)
                r[st][i] = src[(size_t)(c0 + ty + i * 8) * SS + (s0 + st * 32 + tx)];
#pragma unroll
        for (int st = 0; st < 4; st++)
#pragma unroll
            for (int i = 0; i < 4; i++)
                tile[st][ty + i * 8][tx] = r[st][i];
        __syncthreads();

        float* dst = g_xT + (size_t)bz * SS * CIN;
#pragma unroll
        for (int st = 0; st < 4; st++)
#pragma unroll
            for (int i = 0; i < 4; i++)
                dst[(size_t)(s0 + st * 32 + ty + i * 8) * CIN + (c0 + tx)] =
                    tile[st][tx][ty + i * 8];
    } else if (bid < 2592) {
        const int T = (bid - 2304) * 256 + threadIdx.x;
        if (bid == 2304 && threadIdx.x < 256) {
            g_chsum[threadIdx.x] = 0.0f;
            g_chsq[threadIdx.x] = 0.0f;
        }
        const int lane = T & 31;
        const int cb = (T >> 5) & 7;
        const int K8 = T >> 8;
        const int t = K8 >> 2;
        const int tap = t >> 3;
        const int c0 = (t & 7) * 32 + (K8 & 3) * 8 + (lane & 3);
        const int c1 = c0 + 4;
        unsigned r[8];
#pragma unroll
        for (int f = 0; f < 4; f++) {
            const int n = cb * 32 + f * 8 + (lane >> 2);
            r[2 * f]     = f2tf(w[((size_t)n * 256 + c0) * 9 + tap]);
            r[2 * f + 1] = f2tf(w[((size_t)n * 256 + c1) * 9 + tap]);
        }
        g_wFa[(K8 * 8 + cb) * 32 + lane] = make_uint4(r[0], r[1], r[2], r[3]);
        g_wFb[(K8 * 8 + cb) * 32 + lane] = make_uint4(r[4], r[5], r[6], r[7]);
    } else {
        const int T = (bid - 2592) * 256 + threadIdx.x;
        const int lane = T & 31;
        const int wn = (T >> 5) & 1;
        const int K8 = T >> 6;
        const int t = K8 >> 2;
        const int tap = t >> 3;
        const int c0 = (t & 7) * 32 + (K8 & 3) * 8 + (lane & 3);
        const int c1 = c0 + 4;
        unsigned r[4];
#pragma unroll
        for (int fl = 0; fl < 2; fl++) {
            const int n = wn * 16 + fl * 8 + (lane >> 2);
            float v0 = 0.0f, v1 = 0.0f;
            if (n < 27) {
                v0 = w_off[((size_t)n * 256 + c0) * 9 + tap];
                v1 = w_off[((size_t)n * 256 + c1) * 9 + tap];
            }
            r[2 * fl]     = f2tf(v0);
            r[2 * fl + 1] = f2tf(v1);
        }
        g_wOffF[(K8 * 2 + wn) * 32 + lane] = make_uint4(r[0], r[1], r[2], r[3]);
    }
}

// ---------------------------------------------------------------------------
// K1: offset conv as tf32 GEMM + fused bilinear-param epilogue.
// ---------------------------------------------------------------------------
__global__ __launch_bounds__(512, 2) void k_offmma(const float* __restrict__ b_off) {
    __shared__ unsigned Asm[2][128][36];

    const int tid = threadIdx.x;
    const int wid = tid >> 5;
    const int lane = tid & 31;
    const int wm = wid >> 1;
    const int wn = wid & 1;
    const int m0 = blockIdx.x * 128;

    const int pg0 = tid >> 3, pg1 = 64 + pg0;
    const int cp = tid & 7;
    int ph[2], pw_[2], bofs[2], aofs[2];
#pragma unroll
    for (int s = 0; s < 2; s++) {
        const int P = m0 + (s ? pg1 : pg0);
        bofs[s] = (P / SS) * (SS * CIN);
        const int rem = P % SS;
        ph[s] = rem / WW;
        pw_[s] = rem % WW;
    }

    float acc[2][4];
#pragma unroll
    for (int f = 0; f < 2; f++)
#pragma unroll
        for (int c = 0; c < 4; c++) acc[f][c] = 0.0f;

    float4 v[2];

    auto tapsetup = [&](int tap) {
        const int ky = tap / 3 - 1, kx = tap % 3 - 1;
#pragma unroll
        for (int s = 0; s < 2; s++) {
            const int y = ph[s] + ky, x = pw_[s] + kx;
            aofs[s] = (y >= 0 && y < HH && x >= 0 && x < WW)
                          ? bofs[s] + ((y * WW + x) << 8) : -1;
        }
    };
    auto load = [&](int t) {
        const int cb = (t & 7) * 32 + cp * 4;
#pragma unroll
        for (int s = 0; s < 2; s++)
            v[s] = (aofs[s] >= 0) ? *(const float4*)(g_xT + aofs[s] + cb)
                                  : make_float4(0, 0, 0, 0);
    };
    auto store = [&](int buf) {
#pragma unroll
        for (int s = 0; s < 2; s++)
            *(uint4*)&Asm[buf][s ? pg1 : pg0][cp * 4] =
                make_uint4(f2tf(v[s].x), f2tf(v[s].y), f2tf(v[s].z), f2tf(v[s].w));
    };
    auto compute2 = [&](int t, int buf, int q0) {
#pragma unroll
        for (int qq = 0; qq < 2; qq++) {
            const int q = q0 + qq;
            const uint4 B = g_wOffF[((t * 4 + q) * 2 + wn) * 32 + lane];
            const int r = wm * 16 + (lane >> 2);
            const int c = q * 8 + (lane & 3);
            unsigned a[4];
            a[0] = Asm[buf][r][c];
            a[1] = Asm[buf][r + 8][c];
            a[2] = Asm[buf][r][c + 4];
            a[3] = Asm[buf][r + 8][c + 4];
            MMA_TF32(acc[0], a, B.x, B.y);
            MMA_TF32(acc[1], a, B.z, B.w);
        }
    };

    tapsetup(0);
    load(0); store(0);
    __syncthreads();
#pragma unroll 1
    for (int t = 0; t < NKT; t++) {
        const int buf = t & 1;
        const bool more = (t + 1 < NKT);
        if (more && ((t + 1) & 7) == 0) tapsetup((t + 1) >> 3);
        if (more) load(t + 1);
        compute2(t, buf, 0);
        if (more) store(buf ^ 1);
        compute2(t, buf, 2);
        __syncthreads();
    }

    float* E = ((float*)Asm) + wm * (16 * 33);
    const int rr = lane >> 2, cc2 = (lane & 3) * 2;
#pragma unroll
    for (int f = 0; f < 2; f++) {
        const int cbase = wn * 16 + f * 8 + cc2;
        E[rr * 33 + cbase]           = acc[f][0];
        E[rr * 33 + cbase + 1]       = acc[f][1];
        E[(rr + 8) * 33 + cbase]     = acc[f][2];
        E[(rr + 8) * 33 + cbase + 1] = acc[f][3];
    }
    __syncthreads();
    if (wn == 0 && lane < 16) {
        const int P = m0 + wm * 16 + lane;
        const int rem = P % SS;
        const int h = rem / WW, w = rem - (rem / WW) * WW;
        const float* Er = E + lane * 33;
#pragma unroll
        for (int k = 0; k < 9; k++) {
            const float dy = Er[k]      + __ldg(&b_off[k]);
            const float dx = Er[9 + k]  + __ldg(&b_off[9 + k]);
            const float mm = 1.0f / (1.0f + __expf(-(Er[18 + k] + __ldg(&b_off[18 + k]))));
            const float py = (dy + (float)h) + (float)(k / 3 - 1);
            const float px = (dx + (float)w) + (float)(k % 3 - 1);
            const float y0f = floorf(py), x0f = floorf(px);
            const float ly = py - y0f, lx = px - x0f;
            const float vy0 = (y0f >= 0.0f && y0f <= 95.0f) ? 1.0f : 0.0f;
            const float vy1 = (y0f + 1.0f >= 0.0f && y0f + 1.0f <= 95.0f) ? 1.0f : 0.0f;
            const float vx0 = (x0f >= 0.0f && x0f <= 95.0f) ? 1.0f : 0.0f;
            const float vx1 = (x0f + 1.0f >= 0.0f && x0f + 1.0f <= 95.0f) ? 1.0f : 0.0f;
            const int iy0 = (int)fminf(fmaxf(y0f, 0.0f), 95.0f);
            const int iy1 = (int)fminf(fmaxf(y0f + 1.0f, 0.0f), 95.0f);
            const int ix0 = (int)fminf(fmaxf(x0f, 0.0f), 95.0f);
            const int ix1 = (int)fminf(fmaxf(x0f + 1.0f, 0.0f), 95.0f);
            const float w00 = (1.0f - ly) * (1.0f - lx) * vy0 * vx0 * mm;
            const float w01 = (1.0f - ly) * lx          * vy0 * vx1 * mm;
            const float w10 = ly          * (1.0f - lx) * vy1 * vx0 * mm;
            const float w11 = ly          * lx          * vy1 * vx1 * mm;
            g_pw[k * M_TOTAL + P] = make_float4(w00, w01, w10, w11);
            g_pi[k * M_TOTAL + P] = make_int4(iy0 * WW + ix0, iy0 * WW + ix1,
                                              iy1 * WW + ix0, iy1 * WW + ix1);
        }
    }
}

// ---------------------------------------------------------------------------
// K2: main tf32 GEMM, 2m x 8n warps, narrow-window pipeline.
// ---------------------------------------------------------------------------
__global__ __launch_bounds__(512, 1) void k_gemm(const float* __restrict__ bvec,
                                                 float* __restrict__ out) {
    __shared__ unsigned Asm[2][128][36];

    const int tid = threadIdx.x;
    const int wid = tid >> 5;
    const int lane = tid & 31;
    const int wm = wid >> 3;
    const int wn = wid & 7;

    const int m0 = blockIdx.x * 128;
    const int n = m0 / SS;
    const int sb = m0 % SS;
    const float* xbase = g_xT + (size_t)n * SS * CIN;

    const int pg0 = tid >> 3, pg1 = 64 + pg0;
    const int cp = tid & 7;
    const int wbase = wn * 32 + lane;

    float acc[4][4][4];
#pragma unroll
    for (int a = 0; a < 4; a++)
#pragma unroll
        for (int b = 0; b < 4; b++)
#pragma unroll
            for (int c = 0; c < 4; c++) acc[a][b][c] = 0.0f;

    float4 pm[2];
    int4 ii[2];
    float4 v[4];

    auto loadS = [&](int s, int t) {
        const int tap = t >> 3, sub = t & 7;
        if (sub == 0 && s == 0) {
            pm[0] = g_pw[tap * M_TOTAL + m0 + pg0];
            ii[0] = g_pi[tap * M_TOTAL + m0 + pg0];
            pm[1] = g_pw[tap * M_TOTAL + m0 + pg1];
            ii[1] = g_pi[tap * M_TOTAL + m0 + pg1];
        }
        const int cb = sub * 32 + cp * 4;
        v[0] = *(const float4*)(xbase + (ii[s].x << 8) + cb);
        v[1] = *(const float4*)(xbase + (ii[s].y << 8) + cb);
        v[2] = *(const float4*)(xbase + (ii[s].z << 8) + cb);
        v[3] = *(const float4*)(xbase + (ii[s].w << 8) + cb);
    };
    auto storeS = [&](int s, int buf) {
        const float4 w4 = pm[s];
        float a0 = w4.x * v[0].x + w4.y * v[1].x + w4.z * v[2].x + w4.w * v[3].x;
        float a1 = w4.x * v[0].y + w4.y * v[1].y + w4.z * v[2].y + w4.w * v[3].y;
        float a2 = w4.x * v[0].z + w4.y * v[1].z + w4.z * v[2].z + w4.w * v[3].z;
        float a3 = w4.x * v[0].w + w4.y * v[1].w + w4.z * v[2].w + w4.w * v[3].w;
        *(uint4*)&Asm[buf][s ? pg1 : pg0][cp * 4] =
            make_uint4(f2tf(a0), f2tf(a1), f2tf(a2), f2tf(a3));
    };
    auto compute_q = [&](int t, int buf, int q) {
        const int bi = (t * 4 + q) * 256 + wbase;
        const uint4 Ba = g_wFa[bi];
        const uint4 Bb = g_wFb[bi];
#pragma unroll
        for (int mt = 0; mt < 4; mt++) {
            const int r = wm * 64 + mt * 16 + (lane >> 2);
            const int c = q * 8 + (lane & 3);
            unsigned a[4];
            a[0] = Asm[buf][r][c];
            a[1] = Asm[buf][r + 8][c];
            a[2] = Asm[buf][r][c + 4];
            a[3] = Asm[buf][r + 8][c + 4];
            MMA_TF32(acc[mt][0], a, Ba.x, Ba.y);
            MMA_TF32(acc[mt][1], a, Ba.z, Ba.w);
            MMA_TF32(acc[mt][2], a, Bb.x, Bb.y);
            MMA_TF32(acc[mt][3], a, Bb.z, Bb.w);
        }
    };

    loadS(0, 0); storeS(0, 0);
    loadS(1, 0); storeS(1, 0);
    __syncthreads();
#pragma unroll 1
    for (int t = 0; t < NKT; t++) {
        const int buf = t & 1;
        const int nbuf = (t + 1) & 1;
        const bool more = (t + 1 < NKT);
        if (more) loadS(0, t + 1);
        compute_q(t, buf, 0);
        if (more) { storeS(0, nbuf); loadS(1, t + 1); }
        compute_q(t, buf, 1);
        compute_q(t, buf, 2);
        if (more) storeS(1, nbuf);
        compute_q(t, buf, 3);
        __syncthreads();
    }

    // epilogue: +bias, write pre-BN y, per-thread BN partials
    float* Ssm = (float*)&Asm[0][0][0];          // [256][16]
    float* Qsm = Ssm + 4096;                     // [256][16]
    const int slot = wm * 8 + (lane >> 2);
#pragma unroll
    for (int f = 0; f < 4; f++) {
        const int co = wn * 32 + f * 8 + (lane & 3) * 2;
        const float b0 = __ldg(&bvec[co]);
        const float b1 = __ldg(&bvec[co + 1]);
        float* o0 = out + ((size_t)n * COUT + co) * SS + sb + wm * 64 + (lane >> 2);
        float* o1 = o0 + SS;
        float s0 = 0, q0 = 0, s1 = 0, q1 = 0;
#pragma unroll
        for (int mt = 0; mt < 4; mt++) {
            const int r = mt * 16;
            float vv;
            vv = acc[mt][f][0] + b0; o0[r]     = vv; s0 += vv; q0 += vv * vv;
            vv = acc[mt][f][1] + b1; o1[r]     = vv; s1 += vv; q1 += vv * vv;
            vv = acc[mt][f][2] + b0; o0[r + 8] = vv; s0 += vv; q0 += vv * vv;
            vv = acc[mt][f][3] + b1; o1[r + 8] = vv; s1 += vv; q1 += vv * vv;
        }
        Ssm[co * 16 + slot] = s0;  Ssm[(co + 1) * 16 + slot] = s1;
        Qsm[co * 16 + slot] = q0;  Qsm[(co + 1) * 16 + slot] = q1;
    }
    __syncthreads();
    if (tid < 256) {
        float s = 0;
#pragma unroll
        for (int j = 0; j < 16; j++) s += Ssm[tid * 16 + j];
        atomicAdd(&g_chsum[tid], s);
    } else {
        float s = 0;
#pragma unroll
        for (int j = 0; j < 16; j++) s += Qsm[(tid - 256) * 16 + j];
        atomicAdd(&g_chsq[tid - 256], s);
    }
}

// ---------------------------------------------------------------------------
// K4: normalize + ReLU in place, BN finalize inlined.
// ---------------------------------------------------------------------------
__global__ __launch_bounds__(256) void k_norm(float* __restrict__ out,
                                              const float* __restrict__ gamma,
                                              const float* __restrict__ beta) {
    const int co = blockIdx.x & 255;
    const float inv = 1.0f / (float)M_TOTAL;
    const float mean = g_chsum[co] * inv;
    const float var = g_chsq[co] * inv - mean * mean;
    const float sc = __ldg(&gamma[co]) * rsqrtf(var + 1e-5f);
    const float sh = __ldg(&beta[co]) - mean * sc;

    float4* p = (float4*)(out + (size_t)blockIdx.x * SS) + threadIdx.x;
    float4 v[9];
#pragma unroll
    for (int i = 0; i < 9; i++) v[i] = p[i * 256];
#pragma unroll
    for (int i = 0; i < 9; i++) {
        v[i].x = fmaxf(v[i].x * sc + sh, 0.0f);
        v[i].y = fmaxf(v[i].y * sc + sh, 0.0f);
        v[i].z = fmaxf(v[i].z * sc + sh, 0.0f);
        v[i].w = fmaxf(v[i].w * sc + sh, 0.0f);
        p[i * 256] = v[i];
    }
}

// ---------------------------------------------------------------------------
extern "C" void kernel_launch(void* const* d_in, const int* in_sizes, int n_in,
                              void* d_out, int out_size) {
    (void)in_sizes; (void)n_in; (void)out_size;
    const float* x     = (const float*)d_in[0];
    const float* w_off = (const float*)d_in[1];
    const float* b_off = (const float*)d_in[2];
    const float* w     = (const float*)d_in[3];
    const float* b     = (const float*)d_in[4];
    const float* gamma = (const float*)d_in[5];
    const float* beta  = (const float*)d_in[6];
    float* out = (float*)d_out;

    k_prep<<<2664, 256>>>(x, w, w_off);
    k_offmma<<<M_TOTAL / 128, 512>>>(b_off);
    k_gemm<<<M_TOTAL / 128, 512>>>(b, out);
    k_norm<<<NB * COUT, 256>>>(out, gamma, beta);
}

// round 16
// speedup vs baseline: 1.1191x; 1.0455x over previous
#include <cuda_runtime.h>
#include <cuda_bf16.h>

// ---------------------------------------------------------------------------
// DeformConv fused pipeline, round 16:
//  - k_gemm v3: Mtile=64, 256 thr, 2 CTAs/SM (sync-stall hiding); per-pixel
//    wavefronts, regs, and pipeline identical to R13's verified optimum.
//  - k_prep, k_offmma, k_norm byte-identical to R15.
// ---------------------------------------------------------------------------

#define HH 96
#define WW 96
#define SS 9216
#define NB 4
#define CIN 256
#define COUT 256
#define M_TOTAL (NB * SS)      // 36864
#define KDIM (9 * CIN)         // 2304
#define NKT 72                 // k32 tiles

// Scratch
__device__ __align__(16) float g_xT[NB * SS * CIN];        // NHWC x
__device__ __align__(16) uint4 g_wFa[288 * 8 * 32];        // main B frags f0,f1
__device__ __align__(16) uint4 g_wFb[288 * 8 * 32];        // main B frags f2,f3
__device__ __align__(16) uint4 g_wOffF[288 * 2 * 32];      // offset B frags
__device__ __align__(16) float4 g_pw[9 * M_TOTAL];
__device__ __align__(16) int4   g_pi[9 * M_TOTAL];
__device__ float g_chsum[COUT];
__device__ float g_chsq[COUT];

// ---------------- asm helpers ----------------
#define MMA_TF32(d, a, bx, by) \
    asm volatile("mma.sync.aligned.m16n8k8.row.col.f32.tf32.tf32.f32 " \
                 "{%0,%1,%2,%3},{%4,%5,%6,%7},{%8,%9},{%0,%1,%2,%3};" \
                 : "+f"((d)[0]), "+f"((d)[1]), "+f"((d)[2]), "+f"((d)[3]) \
                 : "r"((a)[0]), "r"((a)[1]), "r"((a)[2]), "r"((a)[3]), \
                   "r"(bx), "r"(by))

__device__ __forceinline__ unsigned f2tf(float f) {
    unsigned u;
    asm("cvt.rna.tf32.f32 %0, %1;" : "=r"(u) : "f"(f));
    return u;
}

// ---------------------------------------------------------------------------
// K0: fused prep. Blocks [0,2304): NCHW->NHWC transpose (4 sub-tiles each).
// Blocks [2304,2592): main B frags. Blocks [2592,2664): offset B frags.
// ---------------------------------------------------------------------------
__global__ __launch_bounds__(256) void k_prep(const float* __restrict__ x,
                                              const float* __restrict__ w,
                                              const float* __restrict__ w_off) {
    const int bid = blockIdx.x;
    if (bid < 2304) {
        __shared__ float tile[4][32][33];
        const int bx = bid % 72;
        const int by = (bid / 72) & 7;
        const int bz = bid / 576;
        const int c0 = by * 32;
        const int s0 = bx * 128;
        const int tx = threadIdx.x & 31, ty = threadIdx.x >> 5;
        const float* src = x + (size_t)bz * CIN * SS;

        float r[4][4];
#pragma unroll
        for (int st = 0; st < 4; st++)
#pragma unroll
            for (int i = 0; i < 4; i++)
                r[st][i] = src[(size_t)(c0 + ty + i * 8) * SS + (s0 + st * 32 + tx)];
#pragma unroll
        for (int st = 0; st < 4; st++)
#pragma unroll
            for (int i = 0; i < 4; i++)
                tile[st][ty + i * 8][tx] = r[st][i];
        __syncthreads();

        float* dst = g_xT + (size_t)bz * SS * CIN;
#pragma unroll
        for (int st = 0; st < 4; st++)
#pragma unroll
            for (int i = 0; i < 4; i++)
                dst[(size_t)(s0 + st * 32 + ty + i * 8) * CIN + (c0 + tx)] =
                    tile[st][tx][ty + i * 8];
    } else if (bid < 2592) {
        const int T = (bid - 2304) * 256 + threadIdx.x;
        if (bid == 2304 && threadIdx.x < 256) {
            g_chsum[threadIdx.x] = 0.0f;
            g_chsq[threadIdx.x] = 0.0f;
        }
        const int lane = T & 31;
        const int cb = (T >> 5) & 7;
        const int K8 = T >> 8;
        const int t = K8 >> 2;
        const int tap = t >> 3;
        const int c0 = (t & 7) * 32 + (K8 & 3) * 8 + (lane & 3);
        const int c1 = c0 + 4;
        unsigned r[8];
#pragma unroll
        for (int f = 0; f < 4; f++) {
            const int n = cb * 32 + f * 8 + (lane >> 2);
            r[2 * f]     = f2tf(w[((size_t)n * 256 + c0) * 9 + tap]);
            r[2 * f + 1] = f2tf(w[((size_t)n * 256 + c1) * 9 + tap]);
        }
        g_wFa[(K8 * 8 + cb) * 32 + lane] = make_uint4(r[0], r[1], r[2], r[3]);
        g_wFb[(K8 * 8 + cb) * 32 + lane] = make_uint4(r[4], r[5], r[6], r[7]);
    } else {
        const int T = (bid - 2592) * 256 + threadIdx.x;
        const int lane = T & 31;
        const int wn = (T >> 5) & 1;
        const int K8 = T >> 6;
        const int t = K8 >> 2;
        const int tap = t >> 3;
        const int c0 = (t & 7) * 32 + (K8 & 3) * 8 + (lane & 3);
        const int c1 = c0 + 4;
        unsigned r[4];
#pragma unroll
        for (int fl = 0; fl < 2; fl++) {
            const int n = wn * 16 + fl * 8 + (lane >> 2);
            float v0 = 0.0f, v1 = 0.0f;
            if (n < 27) {
                v0 = w_off[((size_t)n * 256 + c0) * 9 + tap];
                v1 = w_off[((size_t)n * 256 + c1) * 9 + tap];
            }
            r[2 * fl]     = f2tf(v0);
            r[2 * fl + 1] = f2tf(v1);
        }
        g_wOffF[(K8 * 2 + wn) * 32 + lane] = make_uint4(r[0], r[1], r[2], r[3]);
    }
}

// ---------------------------------------------------------------------------
// K1: offset conv as tf32 GEMM + fused bilinear-param epilogue (R15 exact).
// ---------------------------------------------------------------------------
__global__ __launch_bounds__(512, 2) void k_offmma(const float* __restrict__ b_off) {
    __shared__ unsigned Asm[2][128][36];

    const int tid = threadIdx.x;
    const int wid = tid >> 5;
    const int lane = tid & 31;
    const int wm = wid >> 1;
    const int wn = wid & 1;
    const int m0 = blockIdx.x * 128;

    const int pg0 = tid >> 3, pg1 = 64 + pg0;
    const int cp = tid & 7;
    int ph[2], pw_[2], bofs[2], aofs[2];
#pragma unroll
    for (int s = 0; s < 2; s++) {
        const int P = m0 + (s ? pg1 : pg0);
        bofs[s] = (P / SS) * (SS * CIN);
        const int rem = P % SS;
        ph[s] = rem / WW;
        pw_[s] = rem % WW;
    }

    float acc[2][4];
#pragma unroll
    for (int f = 0; f < 2; f++)
#pragma unroll
        for (int c = 0; c < 4; c++) acc[f][c] = 0.0f;

    float4 v[2];

    auto tapsetup = [&](int tap) {
        const int ky = tap / 3 - 1, kx = tap % 3 - 1;
#pragma unroll
        for (int s = 0; s < 2; s++) {
            const int y = ph[s] + ky, x = pw_[s] + kx;
            aofs[s] = (y >= 0 && y < HH && x >= 0 && x < WW)
                          ? bofs[s] + ((y * WW + x) << 8) : -1;
        }
    };
    auto load = [&](int t) {
        const int cb = (t & 7) * 32 + cp * 4;
#pragma unroll
        for (int s = 0; s < 2; s++)
            v[s] = (aofs[s] >= 0) ? *(const float4*)(g_xT + aofs[s] + cb)
                                  : make_float4(0, 0, 0, 0);
    };
    auto store = [&](int buf) {
#pragma unroll
        for (int s = 0; s < 2; s++)
            *(uint4*)&Asm[buf][s ? pg1 : pg0][cp * 4] =
                make_uint4(f2tf(v[s].x), f2tf(v[s].y), f2tf(v[s].z), f2tf(v[s].w));
    };
    auto compute2 = [&](int t, int buf, int q0) {
#pragma unroll
        for (int qq = 0; qq < 2; qq++) {
            const int q = q0 + qq;
            const uint4 B = g_wOffF[((t * 4 + q) * 2 + wn) * 32 + lane];
            const int r = wm * 16 + (lane >> 2);
            const int c = q * 8 + (lane & 3);
            unsigned a[4];
            a[0] = Asm[buf][r][c];
            a[1] = Asm[buf][r + 8][c];
            a[2] = Asm[buf][r][c + 4];
            a[3] = Asm[buf][r + 8][c + 4];
            MMA_TF32(acc[0], a, B.x, B.y);
            MMA_TF32(acc[1], a, B.z, B.w);
        }
    };

    tapsetup(0);
    load(0); store(0);
    __syncthreads();
#pragma unroll 1
    for (int t = 0; t < NKT; t++) {
        const int buf = t & 1;
        const bool more = (t + 1 < NKT);
        if (more && ((t + 1) & 7) == 0) tapsetup((t + 1) >> 3);
        if (more) load(t + 1);
        compute2(t, buf, 0);
        if (more) store(buf ^ 1);
        compute2(t, buf, 2);
        __syncthreads();
    }

    float* E = ((float*)Asm) + wm * (16 * 33);
    const int rr = lane >> 2, cc2 = (lane & 3) * 2;
#pragma unroll
    for (int f = 0; f < 2; f++) {
        const int cbase = wn * 16 + f * 8 + cc2;
        E[rr * 33 + cbase]           = acc[f][0];
        E[rr * 33 + cbase + 1]       = acc[f][1];
        E[(rr + 8) * 33 + cbase]     = acc[f][2];
        E[(rr + 8) * 33 + cbase + 1] = acc[f][3];
    }
    __syncthreads();
    if (wn == 0 && lane < 16) {
        const int P = m0 + wm * 16 + lane;
        const int rem = P % SS;
        const int h = rem / WW, w = rem - (rem / WW) * WW;
        const float* Er = E + lane * 33;
#pragma unroll
        for (int k = 0; k < 9; k++) {
            const float dy = Er[k]      + __ldg(&b_off[k]);
            const float dx = Er[9 + k]  + __ldg(&b_off[9 + k]);
            const float mm = 1.0f / (1.0f + __expf(-(Er[18 + k] + __ldg(&b_off[18 + k]))));
            const float py = (dy + (float)h) + (float)(k / 3 - 1);
            const float px = (dx + (float)w) + (float)(k % 3 - 1);
            const float y0f = floorf(py), x0f = floorf(px);
            const float ly = py - y0f, lx = px - x0f;
            const float vy0 = (y0f >= 0.0f && y0f <= 95.0f) ? 1.0f : 0.0f;
            const float vy1 = (y0f + 1.0f >= 0.0f && y0f + 1.0f <= 95.0f) ? 1.0f : 0.0f;
            const float vx0 = (x0f >= 0.0f && x0f <= 95.0f) ? 1.0f : 0.0f;
            const float vx1 = (x0f + 1.0f >= 0.0f && x0f + 1.0f <= 95.0f) ? 1.0f : 0.0f;
            const int iy0 = (int)fminf(fmaxf(y0f, 0.0f), 95.0f);
            const int iy1 = (int)fminf(fmaxf(y0f + 1.0f, 0.0f), 95.0f);
            const int ix0 = (int)fminf(fmaxf(x0f, 0.0f), 95.0f);
            const int ix1 = (int)fminf(fmaxf(x0f + 1.0f, 0.0f), 95.0f);
            const float w00 = (1.0f - ly) * (1.0f - lx) * vy0 * vx0 * mm;
            const float w01 = (1.0f - ly) * lx          * vy0 * vx1 * mm;
            const float w10 = ly          * (1.0f - lx) * vy1 * vx0 * mm;
            const float w11 = ly          * lx          * vy1 * vx1 * mm;
            g_pw[k * M_TOTAL + P] = make_float4(w00, w01, w10, w11);
            g_pi[k * M_TOTAL + P] = make_int4(iy0 * WW + ix0, iy0 * WW + ix1,
                                              iy1 * WW + ix0, iy1 * WW + ix1);
        }
    }
}

// ---------------------------------------------------------------------------
// K2: main tf32 GEMM v3: Mtile=64, 256 thr (8 n-warps x 32 couts, all rows),
// 2 CTAs/SM for barrier-stall hiding. Narrow-window pipeline unchanged.
// ---------------------------------------------------------------------------
__global__ __launch_bounds__(256, 2) void k_gemm(const float* __restrict__ bvec,
                                                 float* __restrict__ out) {
    __shared__ unsigned Asm[2][64][36];          // 18.4KB -> 2 CTAs/SM

    const int tid = threadIdx.x;
    const int wid = tid >> 5;                    // 0..7 = wn
    const int lane = tid & 31;
    const int wn = wid;

    const int m0 = blockIdx.x * 64;
    const int n = m0 / SS;                       // SS % 64 == 0
    const int sb = m0 % SS;
    const float* xbase = g_xT + (size_t)n * SS * CIN;

    const int pg0 = tid >> 3, pg1 = 32 + pg0;    // 64 pixels, 2 slots
    const int cp = tid & 7;
    const int wbase = wn * 32 + lane;

    float acc[4][4][4];
#pragma unroll
    for (int a = 0; a < 4; a++)
#pragma unroll
        for (int b = 0; b < 4; b++)
#pragma unroll
            for (int c = 0; c < 4; c++) acc[a][b][c] = 0.0f;

    float4 pm[2];
    int4 ii[2];
    float4 v[4];

    auto loadS = [&](int s, int t) {
        const int tap = t >> 3, sub = t & 7;
        if (sub == 0 && s == 0) {
            pm[0] = g_pw[tap * M_TOTAL + m0 + pg0];
            ii[0] = g_pi[tap * M_TOTAL + m0 + pg0];
            pm[1] = g_pw[tap * M_TOTAL + m0 + pg1];
            ii[1] = g_pi[tap * M_TOTAL + m0 + pg1];
        }
        const int cb = sub * 32 + cp * 4;
        v[0] = *(const float4*)(xbase + (ii[s].x << 8) + cb);
        v[1] = *(const float4*)(xbase + (ii[s].y << 8) + cb);
        v[2] = *(const float4*)(xbase + (ii[s].z << 8) + cb);
        v[3] = *(const float4*)(xbase + (ii[s].w << 8) + cb);
    };
    auto storeS = [&](int s, int buf) {
        const float4 w4 = pm[s];
        float a0 = w4.x * v[0].x + w4.y * v[1].x + w4.z * v[2].x + w4.w * v[3].x;
        float a1 = w4.x * v[0].y + w4.y * v[1].y + w4.z * v[2].y + w4.w * v[3].y;
        float a2 = w4.x * v[0].z + w4.y * v[1].z + w4.z * v[2].z + w4.w * v[3].z;
        float a3 = w4.x * v[0].w + w4.y * v[1].w + w4.z * v[2].w + w4.w * v[3].w;
        *(uint4*)&Asm[buf][s ? pg1 : pg0][cp * 4] =
            make_uint4(f2tf(a0), f2tf(a1), f2tf(a2), f2tf(a3));
    };
    auto compute_q = [&](int t, int buf, int q) {
        const int bi = (t * 4 + q) * 256 + wbase;
        const uint4 Ba = g_wFa[bi];
        const uint4 Bb = g_wFb[bi];
#pragma unroll
        for (int mt = 0; mt < 4; mt++) {
            const int r = mt * 16 + (lane >> 2);
            const int c = q * 8 + (lane & 3);
            unsigned a[4];
            a[0] = Asm[buf][r][c];
            a[1] = Asm[buf][r + 8][c];
            a[2] = Asm[buf][r][c + 4];
            a[3] = Asm[buf][r + 8][c + 4];
            MMA_TF32(acc[mt][0], a, Ba.x, Ba.y);
            MMA_TF32(acc[mt][1], a, Ba.z, Ba.w);
            MMA_TF32(acc[mt][2], a, Bb.x, Bb.y);
            MMA_TF32(acc[mt][3], a, Bb.z, Bb.w);
        }
    };

    loadS(0, 0); storeS(0, 0);
    loadS(1, 0); storeS(1, 0);
    __syncthreads();
#pragma unroll 1
    for (int t = 0; t < NKT; t++) {
        const int buf = t & 1;
        const int nbuf = (t + 1) & 1;
        const bool more = (t + 1 < NKT);
        if (more) loadS(0, t + 1);
        compute_q(t, buf, 0);
        if (more) { storeS(0, nbuf); loadS(1, t + 1); }
        compute_q(t, buf, 1);
        compute_q(t, buf, 2);
        if (more) storeS(1, nbuf);
        compute_q(t, buf, 3);
        __syncthreads();
    }

    // epilogue: +bias, write pre-BN y, per-thread BN partials
    float* Ssm = (float*)&Asm[0][0][0];          // [256][8] = 8KB
    float* Qsm = Ssm + 2048;                     // [256][8] = 8KB (16KB < 18.4KB)
    const int slot = lane >> 2;                  // 0..7
#pragma unroll
    for (int f = 0; f < 4; f++) {
        const int co = wn * 32 + f * 8 + (lane & 3) * 2;
        const float b0 = __ldg(&bvec[co]);
        const float b1 = __ldg(&bvec[co + 1]);
        float* o0 = out + ((size_t)n * COUT + co) * SS + sb + (lane >> 2);
        float* o1 = o0 + SS;
        float s0 = 0, q0 = 0, s1 = 0, q1 = 0;
#pragma unroll
        for (int mt = 0; mt < 4; mt++) {
            const int r = mt * 16;
            float vv;
            vv = acc[mt][f][0] + b0; o0[r]     = vv; s0 += vv; q0 += vv * vv;
            vv = acc[mt][f][1] + b1; o1[r]     = vv; s1 += vv; q1 += vv * vv;
            vv = acc[mt][f][2] + b0; o0[r + 8] = vv; s0 += vv; q0 += vv * vv;
            vv = acc[mt][f][3] + b1; o1[r + 8] = vv; s1 += vv; q1 += vv * vv;
        }
        Ssm[co * 8 + slot] = s0;  Ssm[(co + 1) * 8 + slot] = s1;
        Qsm[co * 8 + slot] = q0;  Qsm[(co + 1) * 8 + slot] = q1;
    }
    __syncthreads();
    {
        float s = 0, q = 0;
#pragma unroll
        for (int j = 0; j < 8; j++) { s += Ssm[tid * 8 + j]; q += Qsm[tid * 8 + j]; }
        atomicAdd(&g_chsum[tid], s);
        atomicAdd(&g_chsq[tid], q);
    }
}

// ---------------------------------------------------------------------------
// K4: normalize + ReLU in place, BN finalize inlined (R15 exact).
// ---------------------------------------------------------------------------
__global__ __launch_bounds__(256) void k_norm(float* __restrict__ out,
                                              const float* __restrict__ gamma,
                                              const float* __restrict__ beta) {
    const int co = blockIdx.x & 255;
    const float inv = 1.0f / (float)M_TOTAL;
    const float mean = g_chsum[co] * inv;
    const float var = g_chsq[co] * inv - mean * mean;
    const float sc = __ldg(&gamma[co]) * rsqrtf(var + 1e-5f);
    const float sh = __ldg(&beta[co]) - mean * sc;

    float4* p = (float4*)(out + (size_t)blockIdx.x * SS) + threadIdx.x;
    float4 v[9];
#pragma unroll
    for (int i = 0; i < 9; i++) v[i] = p[i * 256];
#pragma unroll
    for (int i = 0; i < 9; i++) {
        v[i].x = fmaxf(v[i].x * sc + sh, 0.0f);
        v[i].y = fmaxf(v[i].y * sc + sh, 0.0f);
        v[i].z = fmaxf(v[i].z * sc + sh, 0.0f);
        v[i].w = fmaxf(v[i].w * sc + sh, 0.0f);
        p[i * 256] = v[i];
    }
}

// ---------------------------------------------------------------------------
extern "C" void kernel_launch(void* const* d_in, const int* in_sizes, int n_in,
                              void* d_out, int out_size) {
    (void)in_sizes; (void)n_in; (void)out_size;
    const float* x     = (const float*)d_in[0];
    const float* w_off = (const float*)d_in[1];
    const float* b_off = (const float*)d_in[2];
    const float* w     = (const float*)d_in[3];
    const float* b     = (const float*)d_in[4];
    const float* gamma = (const float*)d_in[5];
    const float* beta  = (const float*)d_in[6];
    float* out = (float*)d_out;

    k_prep<<<2664, 256>>>(x, w, w_off);
    k_offmma<<<M_TOTAL / 128, 512>>>(b_off);
    k_gemm<<<M_TOTAL / 64, 256>>>(b, out);
    k_norm<<<NB * COUT, 256>>>(out, gamma, beta);
}

// round 17
// speedup vs baseline: 1.1195x; 1.0003x over previous
#include <cuda_runtime.h>
#include <cuda_bf16.h>

// ---------------------------------------------------------------------------
// DeformConv fused pipeline, round 17:
//  - k_offmma v4: Mtile=64, 256 thr, 4 CTAs/SM (sync-domain multiplication,
//    same mechanism that won R16 on k_gemm).
//  - k_prep, k_gemm, k_norm byte-identical to R16 (best: 389.6us).
// ---------------------------------------------------------------------------

#define HH 96
#define WW 96
#define SS 9216
#define NB 4
#define CIN 256
#define COUT 256
#define M_TOTAL (NB * SS)      // 36864
#define KDIM (9 * CIN)         // 2304
#define NKT 72                 // k32 tiles

// Scratch
__device__ __align__(16) float g_xT[NB * SS * CIN];        // NHWC x
__device__ __align__(16) uint4 g_wFa[288 * 8 * 32];        // main B frags f0,f1
__device__ __align__(16) uint4 g_wFb[288 * 8 * 32];        // main B frags f2,f3
__device__ __align__(16) uint4 g_wOffF[288 * 2 * 32];      // offset B frags
__device__ __align__(16) float4 g_pw[9 * M_TOTAL];
__device__ __align__(16) int4   g_pi[9 * M_TOTAL];
__device__ float g_chsum[COUT];
__device__ float g_chsq[COUT];

// ---------------- asm helpers ----------------
#define MMA_TF32(d, a, bx, by) \
    asm volatile("mma.sync.aligned.m16n8k8.row.col.f32.tf32.tf32.f32 " \
                 "{%0,%1,%2,%3},{%4,%5,%6,%7},{%8,%9},{%0,%1,%2,%3};" \
                 : "+f"((d)[0]), "+f"((d)[1]), "+f"((d)[2]), "+f"((d)[3]) \
                 : "r"((a)[0]), "r"((a)[1]), "r"((a)[2]), "r"((a)[3]), \
                   "r"(bx), "r"(by))

__device__ __forceinline__ unsigned f2tf(float f) {
    unsigned u;
    asm("cvt.rna.tf32.f32 %0, %1;" : "=r"(u) : "f"(f));
    return u;
}

// ---------------------------------------------------------------------------
// K0: fused prep. Blocks [0,2304): NCHW->NHWC transpose (4 sub-tiles each).
// Blocks [2304,2592): main B frags. Blocks [2592,2664): offset B frags.
// ---------------------------------------------------------------------------
__global__ __launch_bounds__(256) void k_prep(const float* __restrict__ x,
                                              const float* __restrict__ w,
                                              const float* __restrict__ w_off) {
    const int bid = blockIdx.x;
    if (bid < 2304) {
        __shared__ float tile[4][32][33];
        const int bx = bid % 72;
        const int by = (bid / 72) & 7;
        const int bz = bid / 576;
        const int c0 = by * 32;
        const int s0 = bx * 128;
        const int tx = threadIdx.x & 31, ty = threadIdx.x >> 5;
        const float* src = x + (size_t)bz * CIN * SS;

        float r[4][4];
#pragma unroll
        for (int st = 0; st < 4; st++)
#pragma unroll
            for (int i = 0; i < 4; i++)
                r[st][i] = src[(size_t)(c0 + ty + i * 8) * SS + (s0 + st * 32 + tx)];
#pragma unroll
        for (int st = 0; st < 4; st++)
#pragma unroll
            for (int i = 0; i < 4; i++)
                tile[st][ty + i * 8][tx] = r[st][i];
        __syncthreads();

        float* dst = g_xT + (size_t)bz * SS * CIN;
#pragma unroll
        for (int st = 0; st < 4; st++)
#pragma unroll
            for (int i = 0; i < 4; i++)
                dst[(size_t)(s0 + st * 32 + ty + i * 8) * CIN + (c0 + tx)] =
                    tile[st][tx][ty + i * 8];
    } else if (bid < 2592) {
        const int T = (bid - 2304) * 256 + threadIdx.x;
        if (bid == 2304 && threadIdx.x < 256) {
            g_chsum[threadIdx.x] = 0.0f;
            g_chsq[threadIdx.x] = 0.0f;
        }
        const int lane = T & 31;
        const int cb = (T >> 5) & 7;
        const int K8 = T >> 8;
        const int t = K8 >> 2;
        const int tap = t >> 3;
        const int c0 = (t & 7) * 32 + (K8 & 3) * 8 + (lane & 3);
        const int c1 = c0 + 4;
        unsigned r[8];
#pragma unroll
        for (int f = 0; f < 4; f++) {
            const int n = cb * 32 + f * 8 + (lane >> 2);
            r[2 * f]     = f2tf(w[((size_t)n * 256 + c0) * 9 + tap]);
            r[2 * f + 1] = f2tf(w[((size_t)n * 256 + c1) * 9 + tap]);
        }
        g_wFa[(K8 * 8 + cb) * 32 + lane] = make_uint4(r[0], r[1], r[2], r[3]);
        g_wFb[(K8 * 8 + cb) * 32 + lane] = make_uint4(r[4], r[5], r[6], r[7]);
    } else {
        const int T = (bid - 2592) * 256 + threadIdx.x;
        const int lane = T & 31;
        const int wn = (T >> 5) & 1;
        const int K8 = T >> 6;
        const int t = K8 >> 2;
        const int tap = t >> 3;
        const int c0 = (t & 7) * 32 + (K8 & 3) * 8 + (lane & 3);
        const int c1 = c0 + 4;
        unsigned r[4];
#pragma unroll
        for (int fl = 0; fl < 2; fl++) {
            const int n = wn * 16 + fl * 8 + (lane >> 2);
            float v0 = 0.0f, v1 = 0.0f;
            if (n < 27) {
                v0 = w_off[((size_t)n * 256 + c0) * 9 + tap];
                v1 = w_off[((size_t)n * 256 + c1) * 9 + tap];
            }
            r[2 * fl]     = f2tf(v0);
            r[2 * fl + 1] = f2tf(v1);
        }
        g_wOffF[(K8 * 2 + wn) * 32 + lane] = make_uint4(r[0], r[1], r[2], r[3]);
    }
}

// ---------------------------------------------------------------------------
// K1: offset conv as tf32 GEMM + fused bilinear-param epilogue.
// v4: Mtile=64, 256 thr (4 m-warps x 2 n-warps), 4 CTAs/SM.
// ---------------------------------------------------------------------------
__global__ __launch_bounds__(256, 4) void k_offmma(const float* __restrict__ b_off) {
    __shared__ unsigned Asm[2][64][36];          // 18.4KB -> 4 CTAs/SM

    const int tid = threadIdx.x;
    const int wid = tid >> 5;                    // 0..7
    const int lane = tid & 31;
    const int wm = wid >> 1;                     // 0..3
    const int wn = wid & 1;
    const int m0 = blockIdx.x * 64;

    const int pg0 = tid >> 3, pg1 = 32 + pg0;    // 64 pixels, 2 slots
    const int cp = tid & 7;
    int ph[2], pw_[2], bofs[2], aofs[2];
#pragma unroll
    for (int s = 0; s < 2; s++) {
        const int P = m0 + (s ? pg1 : pg0);
        bofs[s] = (P / SS) * (SS * CIN);
        const int rem = P % SS;
        ph[s] = rem / WW;
        pw_[s] = rem % WW;
    }

    float acc[2][4];
#pragma unroll
    for (int f = 0; f < 2; f++)
#pragma unroll
        for (int c = 0; c < 4; c++) acc[f][c] = 0.0f;

    float4 v[2];

    auto tapsetup = [&](int tap) {
        const int ky = tap / 3 - 1, kx = tap % 3 - 1;
#pragma unroll
        for (int s = 0; s < 2; s++) {
            const int y = ph[s] + ky, x = pw_[s] + kx;
            aofs[s] = (y >= 0 && y < HH && x >= 0 && x < WW)
                          ? bofs[s] + ((y * WW + x) << 8) : -1;
        }
    };
    auto load = [&](int t) {
        const int cb = (t & 7) * 32 + cp * 4;
#pragma unroll
        for (int s = 0; s < 2; s++)
            v[s] = (aofs[s] >= 0) ? *(const float4*)(g_xT + aofs[s] + cb)
                                  : make_float4(0, 0, 0, 0);
    };
    auto store = [&](int buf) {
#pragma unroll
        for (int s = 0; s < 2; s++)
            *(uint4*)&Asm[buf][s ? pg1 : pg0][cp * 4] =
                make_uint4(f2tf(v[s].x), f2tf(v[s].y), f2tf(v[s].z), f2tf(v[s].w));
    };
    auto compute2 = [&](int t, int buf, int q0) {
#pragma unroll
        for (int qq = 0; qq < 2; qq++) {
            const int q = q0 + qq;
            const uint4 B = g_wOffF[((t * 4 + q) * 2 + wn) * 32 + lane];
            const int r = wm * 16 + (lane >> 2);
            const int c = q * 8 + (lane & 3);
            unsigned a[4];
            a[0] = Asm[buf][r][c];
            a[1] = Asm[buf][r + 8][c];
            a[2] = Asm[buf][r][c + 4];
            a[3] = Asm[buf][r + 8][c + 4];
            MMA_TF32(acc[0], a, B.x, B.y);
            MMA_TF32(acc[1], a, B.z, B.w);
        }
    };

    tapsetup(0);
    load(0); store(0);
    __syncthreads();
#pragma unroll 1
    for (int t = 0; t < NKT; t++) {
        const int buf = t & 1;
        const bool more = (t + 1 < NKT);
        if (more && ((t + 1) & 7) == 0) tapsetup((t + 1) >> 3);
        if (more) load(t + 1);
        compute2(t, buf, 0);
        if (more) store(buf ^ 1);
        compute2(t, buf, 2);
        __syncthreads();
    }

    // ---- fused epilogue: transpose acc into smem, then per-pixel params ----
    float* E = ((float*)Asm) + wm * (16 * 33);   // 4 slabs * 528 * 4B = 8.4KB
    const int rr = lane >> 2, cc2 = (lane & 3) * 2;
#pragma unroll
    for (int f = 0; f < 2; f++) {
        const int cbase = wn * 16 + f * 8 + cc2;
        E[rr * 33 + cbase]           = acc[f][0];
        E[rr * 33 + cbase + 1]       = acc[f][1];
        E[(rr + 8) * 33 + cbase]     = acc[f][2];
        E[(rr + 8) * 33 + cbase + 1] = acc[f][3];
    }
    __syncthreads();
    if (wn == 0 && lane < 16) {
        const int P = m0 + wm * 16 + lane;
        const int rem = P % SS;
        const int h = rem / WW, w = rem - (rem / WW) * WW;
        const float* Er = E + lane * 33;
#pragma unroll
        for (int k = 0; k < 9; k++) {
            const float dy = Er[k]      + __ldg(&b_off[k]);
            const float dx = Er[9 + k]  + __ldg(&b_off[9 + k]);
            const float mm = 1.0f / (1.0f + __expf(-(Er[18 + k] + __ldg(&b_off[18 + k]))));
            const float py = (dy + (float)h) + (float)(k / 3 - 1);
            const float px = (dx + (float)w) + (float)(k % 3 - 1);
            const float y0f = floorf(py), x0f = floorf(px);
            const float ly = py - y0f, lx = px - x0f;
            const float vy0 = (y0f >= 0.0f && y0f <= 95.0f) ? 1.0f : 0.0f;
            const float vy1 = (y0f + 1.0f >= 0.0f && y0f + 1.0f <= 95.0f) ? 1.0f : 0.0f;
            const float vx0 = (x0f >= 0.0f && x0f <= 95.0f) ? 1.0f : 0.0f;
            const float vx1 = (x0f + 1.0f >= 0.0f && x0f + 1.0f <= 95.0f) ? 1.0f : 0.0f;
            const int iy0 = (int)fminf(fmaxf(y0f, 0.0f), 95.0f);
            const int iy1 = (int)fminf(fmaxf(y0f + 1.0f, 0.0f), 95.0f);
            const int ix0 = (int)fminf(fmaxf(x0f, 0.0f), 95.0f);
            const int ix1 = (int)fminf(fmaxf(x0f + 1.0f, 0.0f), 95.0f);
            const float w00 = (1.0f - ly) * (1.0f - lx) * vy0 * vx0 * mm;
            const float w01 = (1.0f - ly) * lx          * vy0 * vx1 * mm;
            const float w10 = ly          * (1.0f - lx) * vy1 * vx0 * mm;
            const float w11 = ly          * lx          * vy1 * vx1 * mm;
            g_pw[k * M_TOTAL + P] = make_float4(w00, w01, w10, w11);
            g_pi[k * M_TOTAL + P] = make_int4(iy0 * WW + ix0, iy0 * WW + ix1,
                                              iy1 * WW + ix0, iy1 * WW + ix1);
        }
    }
}

// ---------------------------------------------------------------------------
// K2: main tf32 GEMM v3 (R16 exact): Mtile=64, 256 thr, 2 CTAs/SM.
// ---------------------------------------------------------------------------
__global__ __launch_bounds__(256, 2) void k_gemm(const float* __restrict__ bvec,
                                                 float* __restrict__ out) {
    __shared__ unsigned Asm[2][64][36];

    const int tid = threadIdx.x;
    const int wid = tid >> 5;
    const int lane = tid & 31;
    const int wn = wid;

    const int m0 = blockIdx.x * 64;
    const int n = m0 / SS;
    const int sb = m0 % SS;
    const float* xbase = g_xT + (size_t)n * SS * CIN;

    const int pg0 = tid >> 3, pg1 = 32 + pg0;
    const int cp = tid & 7;
    const int wbase = wn * 32 + lane;

    float acc[4][4][4];
#pragma unroll
    for (int a = 0; a < 4; a++)
#pragma unroll
        for (int b = 0; b < 4; b++)
#pragma unroll
            for (int c = 0; c < 4; c++) acc[a][b][c] = 0.0f;

    float4 pm[2];
    int4 ii[2];
    float4 v[4];

    auto loadS = [&](int s, int t) {
        const int tap = t >> 3, sub = t & 7;
        if (sub == 0 && s == 0) {
            pm[0] = g_pw[tap * M_TOTAL + m0 + pg0];
            ii[0] = g_pi[tap * M_TOTAL + m0 + pg0];
            pm[1] = g_pw[tap * M_TOTAL + m0 + pg1];
            ii[1] = g_pi[tap * M_TOTAL + m0 + pg1];
        }
        const int cb = sub * 32 + cp * 4;
        v[0] = *(const float4*)(xbase + (ii[s].x << 8) + cb);
        v[1] = *(const float4*)(xbase + (ii[s].y << 8) + cb);
        v[2] = *(const float4*)(xbase + (ii[s].z << 8) + cb);
        v[3] = *(const float4*)(xbase + (ii[s].w << 8) + cb);
    };
    auto storeS = [&](int s, int buf) {
        const float4 w4 = pm[s];
        float a0 = w4.x * v[0].x + w4.y * v[1].x + w4.z * v[2].x + w4.w * v[3].x;
        float a1 = w4.x * v[0].y + w4.y * v[1].y + w4.z * v[2].y + w4.w * v[3].y;
        float a2 = w4.x * v[0].z + w4.y * v[1].z + w4.z * v[2].z + w4.w * v[3].z;
        float a3 = w4.x * v[0].w + w4.y * v[1].w + w4.z * v[2].w + w4.w * v[3].w;
        *(uint4*)&Asm[buf][s ? pg1 : pg0][cp * 4] =
            make_uint4(f2tf(a0), f2tf(a1), f2tf(a2), f2tf(a3));
    };
    auto compute_q = [&](int t, int buf, int q) {
        const int bi = (t * 4 + q) * 256 + wbase;
        const uint4 Ba = g_wFa[bi];
        const uint4 Bb = g_wFb[bi];
#pragma unroll
        for (int mt = 0; mt < 4; mt++) {
            const int r = mt * 16 + (lane >> 2);
            const int c = q * 8 + (lane & 3);
            unsigned a[4];
            a[0] = Asm[buf][r][c];
            a[1] = Asm[buf][r + 8][c];
            a[2] = Asm[buf][r][c + 4];
            a[3] = Asm[buf][r + 8][c + 4];
            MMA_TF32(acc[mt][0], a, Ba.x, Ba.y);
            MMA_TF32(acc[mt][1], a, Ba.z, Ba.w);
            MMA_TF32(acc[mt][2], a, Bb.x, Bb.y);
            MMA_TF32(acc[mt][3], a, Bb.z, Bb.w);
        }
    };

    loadS(0, 0); storeS(0, 0);
    loadS(1, 0); storeS(1, 0);
    __syncthreads();
#pragma unroll 1
    for (int t = 0; t < NKT; t++) {
        const int buf = t & 1;
        const int nbuf = (t + 1) & 1;
        const bool more = (t + 1 < NKT);
        if (more) loadS(0, t + 1);
        compute_q(t, buf, 0);
        if (more) { storeS(0, nbuf); loadS(1, t + 1); }
        compute_q(t, buf, 1);
        compute_q(t, buf, 2);
        if (more) storeS(1, nbuf);
        compute_q(t, buf, 3);
        __syncthreads();
    }

    // epilogue: +bias, write pre-BN y, per-thread BN partials
    float* Ssm = (float*)&Asm[0][0][0];          // [256][8]
    float* Qsm = Ssm + 2048;                     // [256][8]
    const int slot = lane >> 2;
#pragma unroll
    for (int f = 0; f < 4; f++) {
        const int co = wn * 32 + f * 8 + (lane & 3) * 2;
        const float b0 = __ldg(&bvec[co]);
        const float b1 = __ldg(&bvec[co + 1]);
        float* o0 = out + ((size_t)n * COUT + co) * SS + sb + (lane >> 2);
        float* o1 = o0 + SS;
        float s0 = 0, q0 = 0, s1 = 0, q1 = 0;
#pragma unroll
        for (int mt = 0; mt < 4; mt++) {
            const int r = mt * 16;
            float vv;
            vv = acc[mt][f][0] + b0; o0[r]     = vv; s0 += vv; q0 += vv * vv;
            vv = acc[mt][f][1] + b1; o1[r]     = vv; s1 += vv; q1 += vv * vv;
            vv = acc[mt][f][2] + b0; o0[r + 8] = vv; s0 += vv; q0 += vv * vv;
            vv = acc[mt][f][3] + b1; o1[r + 8] = vv; s1 += vv; q1 += vv * vv;
        }
        Ssm[co * 8 + slot] = s0;  Ssm[(co + 1) * 8 + slot] = s1;
        Qsm[co * 8 + slot] = q0;  Qsm[(co + 1) * 8 + slot] = q1;
    }
    __syncthreads();
    {
        float s = 0, q = 0;
#pragma unroll
        for (int j = 0; j < 8; j++) { s += Ssm[tid * 8 + j]; q += Qsm[tid * 8 + j]; }
        atomicAdd(&g_chsum[tid], s);
        atomicAdd(&g_chsq[tid], q);
    }
}

// ---------------------------------------------------------------------------
// K4: normalize + ReLU in place, BN finalize inlined (R16 exact).
// ---------------------------------------------------------------------------
__global__ __launch_bounds__(256) void k_norm(float* __restrict__ out,
                                              const float* __restrict__ gamma,
                                              const float* __restrict__ beta) {
    const int co = blockIdx.x & 255;
    const float inv = 1.0f / (float)M_TOTAL;
    const float mean = g_chsum[co] * inv;
    const float var = g_chsq[co] * inv - mean * mean;
    const float sc = __ldg(&gamma[co]) * rsqrtf(var + 1e-5f);
    const float sh = __ldg(&beta[co]) - mean * sc;

    float4* p = (float4*)(out + (size_t)blockIdx.x * SS) + threadIdx.x;
    float4 v[9];
#pragma unroll
    for (int i = 0; i < 9; i++) v[i] = p[i * 256];
#pragma unroll
    for (int i = 0; i < 9; i++) {
        v[i].x = fmaxf(v[i].x * sc + sh, 0.0f);
        v[i].y = fmaxf(v[i].y * sc + sh, 0.0f);
        v[i].z = fmaxf(v[i].z * sc + sh, 0.0f);
        v[i].w = fmaxf(v[i].w * sc + sh, 0.0f);
        p[i * 256] = v[i];
    }
}

// ---------------------------------------------------------------------------
extern "C" void kernel_launch(void* const* d_in, const int* in_sizes, int n_in,
                              void* d_out, int out_size) {
    (void)in_sizes; (void)n_in; (void)out_size;
    const float* x     = (const float*)d_in[0];
    const float* w_off = (const float*)d_in[1];
    const float* b_off = (const float*)d_in[2];
    const float* w     = (const float*)d_in[3];
    const float* b     = (const float*)d_in[4];
    const float* gamma = (const float*)d_in[5];
    const float* beta  = (const float*)d_in[6];
    float* out = (float*)d_out;

    k_prep<<<2664, 256>>>(x, w, w_off);
    k_offmma<<<M_TOTAL / 64, 256>>>(b_off);
    k_gemm<<<M_TOTAL / 64, 256>>>(b, out);
    k_norm<<<NB * COUT, 256>>>(out, gamma, beta);
}